// round 17
// baseline (speedup 1.0000x reference)
#include <cuda_runtime.h>
#include <cuda_fp16.h>
#include <math_constants.h>

#define N_NODES 20000
#define N_EDGES 640000
#define FIN     128
#define FQK     128
#define FV      128
#define FTOT    384
#define NHEAD   8
#define FH      16

// ---------------- scratch (device globals; no runtime allocation) ----------
__device__ float  g_q  [N_NODES * 128];   // q * 0.25 (fp32)
__device__ __half g_kvh[N_NODES * 256];   // [0:128)=k halves, [128:256)=v halves
__device__ float  g_maxw[NHEAD];          // global per-head max
__device__ int    g_dst [N_EDGES];
__device__ int    g_off [N_NODES + 1];    // CSR row offsets over sorted src
// per-node online-softmax state (pass 1 -> pass 2)
__device__ float g_Sv[N_NODES * 128];     // sum of exp(a-m)*v   (per lane slot)
__device__ float g_Vs[N_NODES * 128];     // sum of v            (per lane slot)
__device__ float g_S1[N_NODES * NHEAD];   // sum of exp(a-m)     (per head)
__device__ float g_m [N_NODES * NHEAD];   // node-local max      (per head)

// ---------------- helpers --------------------------------------------------
__device__ __forceinline__ void atomicMaxF(float* addr, float val) {
    int* ai = (int*)addr;
    int old = *ai;
    while (__int_as_float(old) < val) {
        int assumed = old;
        old = atomicCAS(ai, assumed, __float_as_int(val));
        if (old == assumed) break;
    }
}

// 4 halves (uint2) -> float4
__device__ __forceinline__ float4 h4_to_f4(uint2 u) {
    __half2 a = *(__half2*)&u.x;
    __half2 b = *(__half2*)&u.y;
    float2 f0 = __half22float2(a);
    float2 f1 = __half22float2(b);
    return make_float4(f0.x, f0.y, f1.x, f1.y);
}

__device__ __forceinline__ float dot4(float4 a, float4 b) {
    return a.x * b.x + a.y * b.y + a.z * b.z + a.w * b.w;
}

__device__ __forceinline__ unsigned int f2tf32(float f) {
    unsigned int u;
    asm("cvt.rna.tf32.f32 %0, %1;" : "=r"(u) : "f"(f));
    return u;
}

__device__ __forceinline__ void mma_tf32(float* c, const unsigned int* a,
                                         const unsigned int* b) {
    asm("mma.sync.aligned.m16n8k8.row.col.f32.tf32.tf32.f32 "
        "{%0,%1,%2,%3}, {%4,%5,%6,%7}, {%8,%9}, {%0,%1,%2,%3};"
        : "+f"(c[0]), "+f"(c[1]), "+f"(c[2]), "+f"(c[3])
        : "r"(a[0]), "r"(a[1]), "r"(a[2]), "r"(a[3]), "r"(b[0]), "r"(b[1]));
}

// ---------------- kernel B: detect dtype + dst + CSR offsets + init --------
// Per-block redundant dtype detection: sample int64-interpreted words from the
// middle of the src region (in-bounds under both interpretations). int64 =>
// hi-word 0 and lo-word < N for every sample; int32 => the "hi-word" is a
// sorted src value ~N/4 > 0 -> check fails.
__global__ void convert_kernel(const void* ei, int E, int nnodes) {
    __shared__ int s_ok;
    if (threadIdx.x == 0) s_ok = 1;
    __syncthreads();
    {
        const unsigned int* w = (const unsigned int*)ei;
        int i = E / 4 + (int)(threadIdx.x & 127);
        unsigned int lo = w[2 * i];
        unsigned int hi = w[2 * i + 1];
        if (hi != 0u || lo >= (unsigned int)nnodes) atomicAnd(&s_ok, 0);
    }
    if (blockIdx.x == 0 && threadIdx.x < NHEAD) g_maxw[threadIdx.x] = -CUDART_INF_F;
    __syncthreads();
    const int is64 = s_ok;

    int i = blockIdx.x * blockDim.x + threadIdx.x;
    if (i >= E) return;

    int s, sp;
    if (is64) {
        const long long* p = (const long long*)ei;
        s  = (int)p[i];
        sp = (i == 0) ? -1 : (int)p[i - 1];
        g_dst[i] = (int)p[E + i];
    } else {
        const int* p = (const int*)ei;
        s  = p[i];
        sp = (i == 0) ? -1 : p[i - 1];
        g_dst[i] = p[E + i];
    }
    // CSR offsets: g_off[n] = first edge with src >= n
    for (int n = sp + 1; n <= s; n++) g_off[n] = i;
    if (i == E - 1)
        for (int n = s + 1; n <= nnodes; n++) g_off[n] = E;
}

// ---------------- kernel 1: proj = x @ W^T  (3xTF32 tensor-core) -----------
// C[m][c] = sum_k x[m][k]*W[c][k]. Split x=xh+xl, W=Wh+Wl (tf32) and compute
// xh@Wh + xh@Wl + xl@Wh -> fp32-level accuracy at tensor-core rate.
// Block 256 = 8 warps (4x2); block tile 128(M)x128(N); warp tile 32x64.
// K staged in 8 chunks of 16 (2 k-steps of 8 per chunk).
#define GK    16           // K chunk
#define GPAD  20           // smem row stride (words): (20*r + k) % 32 distinct
__global__ __launch_bounds__(256) void gemm_kernel(
    const float* __restrict__ x, const float* __restrict__ W, int nrows)
{
    __shared__ unsigned int sAh[128][GPAD];
    __shared__ unsigned int sAl[128][GPAD];
    __shared__ unsigned int sBh[128][GPAD];
    __shared__ unsigned int sBl[128][GPAD];

    const int tid  = threadIdx.x;
    const int lane = tid & 31;
    const int wid  = tid >> 5;          // 0..7
    const int wm   = wid >> 1;          // 0..3 -> M offset wm*32
    const int wn   = wid & 1;           // 0..1 -> N offset wn*64
    const int g    = lane >> 2;         // fragment group 0..7
    const int t    = lane & 3;          // thread-in-group 0..3
    const int rowBase = blockIdx.x * 128;
    const int colBase = blockIdx.y * 128;

    float C[2][8][4];
    #pragma unroll
    for (int mi = 0; mi < 2; mi++)
        #pragma unroll
        for (int ni = 0; ni < 8; ni++)
            #pragma unroll
            for (int r = 0; r < 4; r++) C[mi][ni][r] = 0.f;

    const int lr = tid >> 4;            // 0..15 (row group for staging)
    const int lc = tid & 15;            // 0..15 (k within chunk)

    for (int k0 = 0; k0 < FIN; k0 += GK) {
        // stage x chunk [128 rows][16 k] with tf32 hi/lo split
        #pragma unroll
        for (int i = 0; i < 8; i++) {
            int m = lr + i * 16;
            int gr = rowBase + m;
            float val = (gr < nrows) ? x[(size_t)gr * FIN + k0 + lc] : 0.f;
            unsigned int hu = f2tf32(val);
            float lo = val - __uint_as_float(hu);
            sAh[m][lc] = hu;
            sAl[m][lc] = f2tf32(lo);
        }
        // stage W chunk [128 n][16 k]
        #pragma unroll
        for (int i = 0; i < 8; i++) {
            int n = lr + i * 16;
            float val = W[(size_t)(colBase + n) * FIN + k0 + lc];
            unsigned int hu = f2tf32(val);
            float lo = val - __uint_as_float(hu);
            sBh[n][lc] = hu;
            sBl[n][lc] = f2tf32(lo);
        }
        __syncthreads();

        #pragma unroll
        for (int s = 0; s < 2; s++) {
            const int kk = s * 8;
            unsigned int Ah[2][4], Al[2][4];
            #pragma unroll
            for (int mi = 0; mi < 2; mi++) {
                int r0 = wm * 32 + mi * 16 + g;
                Ah[mi][0] = sAh[r0][kk + t];
                Ah[mi][1] = sAh[r0 + 8][kk + t];
                Ah[mi][2] = sAh[r0][kk + t + 4];
                Ah[mi][3] = sAh[r0 + 8][kk + t + 4];
                Al[mi][0] = sAl[r0][kk + t];
                Al[mi][1] = sAl[r0 + 8][kk + t];
                Al[mi][2] = sAl[r0][kk + t + 4];
                Al[mi][3] = sAl[r0 + 8][kk + t + 4];
            }
            #pragma unroll
            for (int ni = 0; ni < 8; ni++) {
                int n = wn * 64 + ni * 8 + g;
                unsigned int Bh[2], Bl[2];
                Bh[0] = sBh[n][kk + t];
                Bh[1] = sBh[n][kk + t + 4];
                Bl[0] = sBl[n][kk + t];
                Bl[1] = sBl[n][kk + t + 4];
                #pragma unroll
                for (int mi = 0; mi < 2; mi++) {
                    mma_tf32(C[mi][ni], Ah[mi], Bh);
                    mma_tf32(C[mi][ni], Ah[mi], Bl);
                    mma_tf32(C[mi][ni], Al[mi], Bh);
                }
            }
        }
        __syncthreads();
    }

    // epilogue: q (colBase 0) -> fp32 * 0.25; k/v -> fp16 g_kvh
    #pragma unroll
    for (int mi = 0; mi < 2; mi++) {
        #pragma unroll
        for (int half = 0; half < 2; half++) {        // c0,c1 vs c2,c3
            int gr = rowBase + wm * 32 + mi * 16 + g + half * 8;
            if (gr >= nrows) continue;
            #pragma unroll
            for (int ni = 0; ni < 8; ni++) {
                float c0 = C[mi][ni][half * 2];
                float c1 = C[mi][ni][half * 2 + 1];
                int gc = colBase + wn * 64 + ni * 8 + 2 * t;
                if (colBase == 0) {
                    float2 qq = make_float2(c0 * 0.25f, c1 * 0.25f);
                    *(float2*)(g_q + (size_t)gr * 128 + gc) = qq;
                } else {
                    int o = gc - 128;                  // k: [0,128), v: [128,256)
                    *(__half2*)(g_kvh + (size_t)gr * 256 + o) =
                        __floats2half2_rn(c0, c1);
                }
            }
        }
    }
}

// ---------------- kernel 2: fused logits + online softmax (4-edge unroll) --
// One warp per node (strided). q row register-resident (fp32); per 4 edges
// gather k+v half-rows (8 independent 8B loads) -> 4 overlapping shuffle/exp
// chains, merged once per group. Lane l: head h=l>>2.
__global__ __launch_bounds__(256, 4) void attn_kernel(int nnodes)
{
    const int lane   = threadIdx.x & 31;
    const int warp   = (blockIdx.x * blockDim.x + threadIdx.x) >> 5;
    const int nwarps = (gridDim.x * blockDim.x) >> 5;
    const int h = lane >> 2;

    float runmax = -CUDART_INF_F;

    for (int n = warp; n < nnodes; n += nwarps) {
        const int lo = g_off[n], hi = g_off[n + 1];
        if (hi <= lo) continue;

        const float4 qv = *(const float4*)(g_q + n * 128 + lane * 4);

        float m  = -CUDART_INF_F;
        float S1 = 0.f;
        float4 Sv = make_float4(0.f, 0.f, 0.f, 0.f);
        float4 Vs = make_float4(0.f, 0.f, 0.f, 0.f);

        int e = lo;
        for (; e + 4 <= hi; e += 4) {
            const int d0 = g_dst[e],     d1 = g_dst[e + 1];
            const int d2 = g_dst[e + 2], d3 = g_dst[e + 3];
            const __half* p0 = g_kvh + d0 * 256 + lane * 4;
            const __half* p1 = g_kvh + d1 * 256 + lane * 4;
            const __half* p2 = g_kvh + d2 * 256 + lane * 4;
            const __half* p3 = g_kvh + d3 * 256 + lane * 4;
            const uint2 ku0 = *(const uint2*)p0;
            const uint2 ku1 = *(const uint2*)p1;
            const uint2 ku2 = *(const uint2*)p2;
            const uint2 ku3 = *(const uint2*)p3;
            const uint2 vu0 = *(const uint2*)(p0 + 128);
            const uint2 vu1 = *(const uint2*)(p1 + 128);
            const uint2 vu2 = *(const uint2*)(p2 + 128);
            const uint2 vu3 = *(const uint2*)(p3 + 128);

            float t0 = dot4(qv, h4_to_f4(ku0));
            float t1 = dot4(qv, h4_to_f4(ku1));
            float t2 = dot4(qv, h4_to_f4(ku2));
            float t3 = dot4(qv, h4_to_f4(ku3));
            t0 += __shfl_xor_sync(0xFFFFFFFFu, t0, 1);
            t1 += __shfl_xor_sync(0xFFFFFFFFu, t1, 1);
            t2 += __shfl_xor_sync(0xFFFFFFFFu, t2, 1);
            t3 += __shfl_xor_sync(0xFFFFFFFFu, t3, 1);
            t0 += __shfl_xor_sync(0xFFFFFFFFu, t0, 2);
            t1 += __shfl_xor_sync(0xFFFFFFFFu, t1, 2);
            t2 += __shfl_xor_sync(0xFFFFFFFFu, t2, 2);
            t3 += __shfl_xor_sync(0xFFFFFFFFu, t3, 2);

            float mg   = fmaxf(fmaxf(t0, t1), fmaxf(t2, t3));
            float mnew = fmaxf(m, mg);
            float sc = __expf(m - mnew);     // 0 on first group (m=-inf)
            float w0 = __expf(t0 - mnew);
            float w1 = __expf(t1 - mnew);
            float w2 = __expf(t2 - mnew);
            float w3 = __expf(t3 - mnew);
            m = mnew;
            S1 = S1 * sc + ((w0 + w1) + (w2 + w3));

            const float4 v0 = h4_to_f4(vu0);
            const float4 v1 = h4_to_f4(vu1);
            const float4 v2 = h4_to_f4(vu2);
            const float4 v3 = h4_to_f4(vu3);
            Sv.x = Sv.x * sc + ((w0 * v0.x + w1 * v1.x) + (w2 * v2.x + w3 * v3.x));
            Sv.y = Sv.y * sc + ((w0 * v0.y + w1 * v1.y) + (w2 * v2.y + w3 * v3.y));
            Sv.z = Sv.z * sc + ((w0 * v0.z + w1 * v1.z) + (w2 * v2.z + w3 * v3.z));
            Sv.w = Sv.w * sc + ((w0 * v0.w + w1 * v1.w) + (w2 * v2.w + w3 * v3.w));
            Vs.x += (v0.x + v1.x) + (v2.x + v3.x);
            Vs.y += (v0.y + v1.y) + (v2.y + v3.y);
            Vs.z += (v0.z + v1.z) + (v2.z + v3.z);
            Vs.w += (v0.w + v1.w) + (v2.w + v3.w);
        }
        for (; e < hi; e++) {
            const int d = g_dst[e];
            const __half* p0 = g_kvh + d * 256 + lane * 4;
            const float4 kv = h4_to_f4(*(const uint2*)p0);
            const float4 vv = h4_to_f4(*(const uint2*)(p0 + 128));
            float t = dot4(qv, kv);
            t += __shfl_xor_sync(0xFFFFFFFFu, t, 1);
            t += __shfl_xor_sync(0xFFFFFFFFu, t, 2);
            float mnew = fmaxf(m, t);
            float sc = __expf(m - mnew);
            float w  = __expf(t - mnew);
            m = mnew;
            S1 = S1 * sc + w;
            Sv.x = Sv.x * sc + w * vv.x;
            Sv.y = Sv.y * sc + w * vv.y;
            Sv.z = Sv.z * sc + w * vv.z;
            Sv.w = Sv.w * sc + w * vv.w;
            Vs.x += vv.x; Vs.y += vv.y; Vs.z += vv.z; Vs.w += vv.w;
        }

        // store per-node state (coalesced 512B per warp for Sv/Vs)
        *(float4*)(g_Sv + n * 128 + lane * 4) = Sv;
        *(float4*)(g_Vs + n * 128 + lane * 4) = Vs;
        if ((lane & 3) == 0) {
            g_S1[n * NHEAD + h] = S1;
            g_m [n * NHEAD + h] = m;
        }
        runmax = fmaxf(runmax, m);
    }

    // hierarchical per-head max: registers -> shared -> global
    __shared__ float smax[NHEAD];
    if (threadIdx.x < NHEAD) smax[threadIdx.x] = -CUDART_INF_F;
    __syncthreads();
    if ((lane & 3) == 0 && runmax > -CUDART_INF_F) atomicMaxF(&smax[h], runmax);
    __syncthreads();
    if (threadIdx.x < NHEAD && smax[threadIdx.x] > -CUDART_INF_F)
        atomicMaxF(&g_maxw[threadIdx.x], smax[threadIdx.x]);
}

// ---------------- kernel 3: per-node finalize (no edge traversal) ----------
// out = (s*Sv + eps*Vs) / (s*S1 + eps*deg),  s = exp(m - mx)
__global__ __launch_bounds__(256) void finalize_kernel(
    float* __restrict__ out, int nnodes)
{
    const int lane = threadIdx.x & 31;
    const int n    = (blockIdx.x * blockDim.x + threadIdx.x) >> 5;
    if (n >= nnodes) return;

    int deg = g_off[n + 1] - g_off[n];
    float4 res = make_float4(0.f, 0.f, 0.f, 0.f);
    if (deg > 0) {
        const int h = lane >> 2;
        float s  = __expf(g_m[n * NHEAD + h] - g_maxw[h]);
        float S1 = g_S1[n * NHEAD + h];
        float4 Sv = *(const float4*)(g_Sv + n * 128 + lane * 4);
        float4 Vs = *(const float4*)(g_Vs + n * 128 + lane * 4);
        float inv = 1.f / (s * S1 + 1e-8f * (float)deg);
        res.x = (s * Sv.x + 1e-8f * Vs.x) * inv;
        res.y = (s * Sv.y + 1e-8f * Vs.y) * inv;
        res.z = (s * Sv.z + 1e-8f * Vs.z) * inv;
        res.w = (s * Sv.w + 1e-8f * Vs.w) * inv;
    }
    ((float4*)out)[(size_t)n * 32 + lane] = res;   // coalesced 512B store
}

// ---------------- launch ---------------------------------------------------
extern "C" void kernel_launch(void* const* d_in, const int* in_sizes, int n_in,
                              void* d_out, int out_size)
{
    const float* x  = (const float*)d_in[0];          // [N, 128]
    const float* W  = (const float*)d_in[1];          // [384, 128]
    // d_in[2] = batch (unused by reference math)
    const void*  ei = d_in[3];                        // [2, E], int32 or int64
    float* out = (float*)d_out;

    const int nrows = in_sizes[0] / FIN;
    const int E     = in_sizes[3] / 2;

    convert_kernel<<<(E + 255) / 256, 256>>>(ei, E, nrows);

    dim3 ggrid((nrows + 127) / 128, FTOT / 128);
    gemm_kernel<<<ggrid, 256>>>(x, W, nrows);

    attn_kernel<<<1250, 256>>>(nrows);                // 10000 warps, 2 nodes/warp

    finalize_kernel<<<(nrows * 32 + 255) / 256, 256>>>(out, nrows);
}